// round 1
// baseline (speedup 1.0000x reference)
#include <cuda_runtime.h>
#include <cstdint>
#include <cstddef>

#define NB 64
#define NH 12
#define NP 197
#define ND 64
#define TOPK 10
#define NSLOT 7
#define FULLMASK 0xffffffffu

// Global double accumulator for the MSE sum (device global: no allocation).
__device__ double g_acc;

// ---- float <-> order-preserving u32 key --------------------------------
__device__ __forceinline__ unsigned f2key(float f) {
    int u = __float_as_int(f);
    int mask = (u >> 31) | 0x80000000;     // pos: 0x80000000, neg: 0xFFFFFFFF
    return (unsigned)(u ^ mask);
}
__device__ __forceinline__ float key2f(unsigned k) {
    unsigned u = (k & 0x80000000u) ? (k ^ 0x80000000u) : ~k;
    return __int_as_float((int)u);
}

__device__ __forceinline__ void ce_desc(unsigned& a, unsigned& b) {
    unsigned mx = a > b ? a : b;
    unsigned mn = a > b ? b : a;
    a = mx; b = mn;
}

// Process one att row of NP logits against a v tile in SMEM.
// Returns this lane's 2 output components: d = 2*lane and 2*lane+1.
__device__ __forceinline__ float2 process_row(const float* __restrict__ row,
                                              const float* __restrict__ vsh,
                                              int lane) {
    const float NEG_INF = __int_as_float(0xff800000);

    // Load 7 slots per lane (coalesced: slot k covers indices k*32+lane).
    float y[NSLOT];
#pragma unroll
    for (int k = 0; k < 6; ++k) y[k] = row[k * 32 + lane];
    y[6] = (lane < NP - 192) ? row[192 + lane] : NEG_INF;

    // Order-preserving u32 keys, sorted descending per lane
    // (odd-even transposition, 7 rounds, provably correct).
    unsigned s[NSLOT];
#pragma unroll
    for (int k = 0; k < NSLOT; ++k) s[k] = f2key(y[k]);
#pragma unroll
    for (int r = 0; r < 7; ++r) {
        if (r & 1) { ce_desc(s[1], s[2]); ce_desc(s[3], s[4]); ce_desc(s[5], s[6]); }
        else       { ce_desc(s[0], s[1]); ce_desc(s[2], s[3]); ce_desc(s[4], s[5]); }
    }

    // Pop the warp-wide max TOPK-1 times; the TOPK-th max is the threshold.
    unsigned mkey = 0u;
#pragma unroll
    for (int it = 0; it < TOPK - 1; ++it) {
        unsigned wm = __reduce_max_sync(FULLMASK, s[0]);
        if (it == 0) mkey = wm;
        if (s[0] == wm) {   // this lane owns the popped value: shift its sorted list
            s[0] = s[1]; s[1] = s[2]; s[2] = s[3];
            s[3] = s[4]; s[4] = s[5]; s[5] = s[6]; s[6] = 0u;
        }
    }
    unsigned tkey = __reduce_max_sync(FULLMASK, s[0]);
    float m      = key2f(mkey);   // row max (for exp stability)
    float thresh = key2f(tkey);   // 10th-largest logit

    // Weighted gather: out = sum_sel e^{y-m} * v[i,:] / sum_sel e^{y-m}
    float2 acc = make_float2(0.f, 0.f);
    float ws = 0.f;
    const float2* __restrict__ v2 = reinterpret_cast<const float2*>(vsh);
#pragma unroll
    for (int k = 0; k < NSLOT; ++k) {
        float w = __expf(y[k] - m);                       // exp2-based fast exp
        unsigned bal = __ballot_sync(FULLMASK, y[k] >= thresh);
        while (bal) {
            int j = __ffs(bal) - 1;
            bal &= bal - 1;
            float wj = __shfl_sync(FULLMASK, w, j);
            int i = (k << 5) + j;                         // selected key index
            float2 vv = v2[i * 32 + lane];                // d = 2*lane, 2*lane+1
            acc.x = fmaf(wj, vv.x, acc.x);
            acc.y = fmaf(wj, vv.y, acc.y);
            ws += wj;
        }
    }
    float inv = __fdividef(1.0f, ws);
    return make_float2(acc.x * inv, acc.y * inv);
}

__global__ void hintop_zero() { g_acc = 0.0; }

__global__ void __launch_bounds__(256, 2)
hintop_main(const float* __restrict__ att_s, const float* __restrict__ att_t,
            const float* __restrict__ v_s,   const float* __restrict__ v_t) {
    extern __shared__ float smem_v[];           // [2][NP*ND] floats (100,864 B)
    const int bh = blockIdx.x;                  // (b*H + h), 0..767

    float* vsS = smem_v;
    float* vsT = smem_v + NP * ND;
    {
        const float4* a4 = reinterpret_cast<const float4*>(v_s + (size_t)bh * NP * ND);
        const float4* b4 = reinterpret_cast<const float4*>(v_t + (size_t)bh * NP * ND);
        float4* s4 = reinterpret_cast<float4*>(vsS);
        float4* t4 = reinterpret_cast<float4*>(vsT);
        for (int i = threadIdx.x; i < NP * ND / 4; i += 256) {
            s4[i] = a4[i];
            t4[i] = b4[i];
        }
    }
    __syncthreads();

    const int warp = threadIdx.x >> 5;
    const int lane = threadIdx.x & 31;
    const float* aS = att_s + (size_t)bh * NP * NP;
    const float* aT = att_t + (size_t)bh * NP * NP;

    float lsum = 0.f;
    for (int p = warp; p < NP; p += 8) {
        float2 os = process_row(aS + (size_t)p * NP, vsS, lane);
        float2 ot = process_row(aT + (size_t)p * NP, vsT, lane);
        float dx = os.x - ot.x;
        float dy = os.y - ot.y;
        lsum = fmaf(dx, dx, lsum);
        lsum = fmaf(dy, dy, lsum);
    }

    // warp reduce, then block reduce, one double atomic per block
#pragma unroll
    for (int off = 16; off; off >>= 1) lsum += __shfl_xor_sync(FULLMASK, lsum, off);

    __shared__ float wsum_sh[8];
    if (lane == 0) wsum_sh[warp] = lsum;
    __syncthreads();
    if (threadIdx.x == 0) {
        float t = 0.f;
#pragma unroll
        for (int w = 0; w < 8; ++w) t += wsum_sh[w];
        atomicAdd(&g_acc, (double)t);
    }
}

__global__ void hintop_fin(float* out) {
    out[0] = (float)(g_acc / (double)((size_t)NB * NH * NP * ND));
}

extern "C" void kernel_launch(void* const* d_in, const int* in_sizes, int n_in,
                              void* d_out, int out_size) {
    const float* att_s = (const float*)d_in[0];
    const float* att_t = (const float*)d_in[1];
    const float* v_s   = (const float*)d_in[2];
    const float* v_t   = (const float*)d_in[3];

    const int smem_bytes = 2 * NP * ND * (int)sizeof(float);   // 100,864 B
    cudaFuncSetAttribute(hintop_main, cudaFuncAttributeMaxDynamicSharedMemorySize,
                         smem_bytes);

    hintop_zero<<<1, 1>>>();
    hintop_main<<<NB * NH, 256, smem_bytes>>>(att_s, att_t, v_s, v_t);
    hintop_fin<<<1, 1>>>((float*)d_out);
}

// round 2
// speedup vs baseline: 1.9203x; 1.9203x over previous
#include <cuda_runtime.h>
#include <cstdint>
#include <cstddef>

#define NB 64
#define NH 12
#define NP 197
#define ND 64
#define TOPK 10
#define NSLOT 7
#define FULLMASK 0xffffffffu

// Persistent device state (statically initialized; last block resets -> replay-safe)
__device__ double g_acc = 0.0;
__device__ unsigned g_done = 0;

// float -> order-preserving u32 key, low 8 bits replaced by source index.
// Monotone in f up to a <=256-ulp perturbation (3e-5 relative): acceptable.
__device__ __forceinline__ unsigned key_pack(float f, unsigned idx) {
    int u = __float_as_int(f);
    unsigned mask = ((unsigned)(u >> 31)) | 0x80000000u;
    return (((unsigned)u ^ mask) & 0xFFFFFF00u) | idx;
}
__device__ __forceinline__ float key2f(unsigned k) {
    unsigned mask = (unsigned)(~(((int)k) >> 31)) | 0x80000000u;
    return __int_as_float((int)(k ^ mask));
}

// descending compare-exchange (2x IMNMX.U32)
__device__ __forceinline__ void ce(unsigned& a, unsigned& b) {
    unsigned mx = a > b ? a : b;
    unsigned mn = a > b ? b : a;
    a = mx; b = mn;
}
// Batcher odd-even mergesort for 8 with element 7 = constant-min (dropped
// comparators (6,7),(5,7),(3,7) are no-ops) -> provably correct 16-CE sort-7.
__device__ __forceinline__ void sort7(unsigned s[NSLOT]) {
    ce(s[0],s[1]); ce(s[2],s[3]); ce(s[4],s[5]);
    ce(s[0],s[2]); ce(s[1],s[3]); ce(s[4],s[6]);
    ce(s[1],s[2]); ce(s[5],s[6]);
    ce(s[0],s[4]); ce(s[1],s[5]); ce(s[2],s[6]);
    ce(s[2],s[4]); ce(s[3],s[5]);
    ce(s[1],s[2]); ce(s[3],s[4]); ce(s[5],s[6]);
}

__device__ __forceinline__ void load_row(float y[NSLOT], const float* __restrict__ row,
                                         int lane) {
    const float NEG_INF = __int_as_float(0xff800000);
#pragma unroll
    for (int k = 0; k < 6; ++k) y[k] = row[k * 32 + lane];
    y[6] = (lane < NP - 192) ? row[192 + lane] : NEG_INF;
}

__global__ void __launch_bounds__(256, 2)
hintop_main(const float* __restrict__ att_s, const float* __restrict__ att_t,
            const float* __restrict__ v_s,   const float* __restrict__ v_t,
            float* __restrict__ out) {
    extern __shared__ float smem_v[];           // [2][NP*ND] floats (100,864 B)
    const int bh = blockIdx.x;                  // (b*H + h), 0..767
    const int warp = threadIdx.x >> 5;
    const int lane = threadIdx.x & 31;

    float* vsS = smem_v;
    float* vsT = smem_v + NP * ND;
    {
        const float4* a4 = reinterpret_cast<const float4*>(v_s + (size_t)bh * NP * ND);
        const float4* b4 = reinterpret_cast<const float4*>(v_t + (size_t)bh * NP * ND);
        float4* s4 = reinterpret_cast<float4*>(vsS);
        float4* t4 = reinterpret_cast<float4*>(vsT);
        for (int i = threadIdx.x; i < NP * ND / 4; i += 256) {
            s4[i] = a4[i];
            t4[i] = b4[i];
        }
    }
    __syncthreads();

    const float* aS = att_s + (size_t)bh * NP * NP;
    const float* aT = att_t + (size_t)bh * NP * NP;
    // per-lane base for the float2 gather (d = 2*lane, 2*lane+1)
    const float2* __restrict__ v2S = reinterpret_cast<const float2*>(vsS) + lane;
    const float2* __restrict__ v2T = reinterpret_cast<const float2*>(vsT) + lane;

    float lsum = 0.f;

    int p = warp;
    float cS[NSLOT], cT[NSLOT];
    if (p < NP) {
        load_row(cS, aS + (size_t)p * NP, lane);
        load_row(cT, aT + (size_t)p * NP, lane);
    }

    while (p < NP) {
        const int pn = p + 8;

        // Build packed keys and sort each lane's 7 descending (S and T interleaved).
        unsigned sS[NSLOT], sT[NSLOT];
#pragma unroll
        for (int k = 0; k < NSLOT; ++k) {
            unsigned idx = (unsigned)(k * 32 + lane);
            sS[k] = key_pack(cS[k], idx);
            sT[k] = key_pack(cT[k], idx);
        }
        sort7(sS);
        sort7(sT);

        // Prefetch next pair of rows: LDG latency overlaps sort+pop phase.
        float nS[NSLOT], nT[NSLOT];
        const bool more = (pn < NP);
        if (more) {
            load_row(nS, aS + (size_t)pn * NP, lane);
            load_row(nT, aT + (size_t)pn * NP, lane);
        }

        // Pop the warp-wide top-10; each pop yields (value,index) uniformly.
        float2 accS = make_float2(0.f, 0.f), accT = make_float2(0.f, 0.f);
        float wsS = 0.f, wsT = 0.f;
#pragma unroll
        for (int it = 0; it < TOPK; ++it) {
            unsigned wmS = __reduce_max_sync(FULLMASK, sS[0]);
            unsigned wmT = __reduce_max_sync(FULLMASK, sT[0]);

            if (it < TOPK - 1) {                // owner lane shifts its sorted list
                bool hS = (sS[0] == wmS);
#pragma unroll
                for (int k = 0; k < NSLOT - 1; ++k) sS[k] = hS ? sS[k + 1] : sS[k];
                sS[NSLOT - 1] = hS ? 0u : sS[NSLOT - 1];
                bool hT = (sT[0] == wmT);
#pragma unroll
                for (int k = 0; k < NSLOT - 1; ++k) sT[k] = hT ? sT[k + 1] : sT[k];
                sT[NSLOT - 1] = hT ? 0u : sT[NSLOT - 1];
            }

            unsigned iS = wmS & 0xFFu;          // packed index == k*32+lane
            unsigned iT = wmT & 0xFFu;
            float wS = __expf(key2f(wmS));      // normalizer cancels max-subtraction
            float wT = __expf(key2f(wmT));
            float2 vvS = v2S[iS * 32];
            float2 vvT = v2T[iT * 32];
            accS.x = fmaf(wS, vvS.x, accS.x);
            accS.y = fmaf(wS, vvS.y, accS.y);
            wsS += wS;
            accT.x = fmaf(wT, vvT.x, accT.x);
            accT.y = fmaf(wT, vvT.y, accT.y);
            wsT += wT;
        }

        float invS = __fdividef(1.0f, wsS);
        float invT = __fdividef(1.0f, wsT);
        float dx = accS.x * invS - accT.x * invT;
        float dy = accS.y * invS - accT.y * invT;
        lsum = fmaf(dx, dx, lsum);
        lsum = fmaf(dy, dy, lsum);

        p = pn;
        if (more) {
#pragma unroll
            for (int k = 0; k < NSLOT; ++k) { cS[k] = nS[k]; cT[k] = nT[k]; }
        }
    }

    // warp reduce -> block reduce -> one double atomic; last block finalizes.
#pragma unroll
    for (int off = 16; off; off >>= 1) lsum += __shfl_xor_sync(FULLMASK, lsum, off);

    __shared__ float wsum_sh[8];
    if (lane == 0) wsum_sh[warp] = lsum;
    __syncthreads();
    if (threadIdx.x == 0) {
        float t = 0.f;
#pragma unroll
        for (int w = 0; w < 8; ++w) t += wsum_sh[w];
        atomicAdd(&g_acc, (double)t);
        __threadfence();
        unsigned ticket = atomicAdd(&g_done, 1);
        if (ticket == (unsigned)(gridDim.x - 1)) {       // last block to finish
            __threadfence();
            double total = atomicAdd(&g_acc, 0.0);       // read via L2
            out[0] = (float)(total / (double)((size_t)NB * NH * NP * ND));
            g_acc = 0.0;                                 // reset for next replay
            g_done = 0;
            __threadfence();
        }
    }
}

extern "C" void kernel_launch(void* const* d_in, const int* in_sizes, int n_in,
                              void* d_out, int out_size) {
    const float* att_s = (const float*)d_in[0];
    const float* att_t = (const float*)d_in[1];
    const float* v_s   = (const float*)d_in[2];
    const float* v_t   = (const float*)d_in[3];

    const int smem_bytes = 2 * NP * ND * (int)sizeof(float);   // 100,864 B
    cudaFuncSetAttribute(hintop_main, cudaFuncAttributeMaxDynamicSharedMemorySize,
                         smem_bytes);

    hintop_main<<<NB * NH, 256, smem_bytes>>>(att_s, att_t, v_s, v_t, (float*)d_out);
}